// round 15
// baseline (speedup 1.0000x reference)
#include <cuda_runtime.h>
#include <cuda.h>
#include <cuda_fp16.h>
#include <math.h>
#include <stdint.h>

// ---------------- problem constants ----------------
#define NT      16384
#define DIM     2048
#define NE      64
#define TOPK    8
#define TILE_M  64
#define KC      64
#define NCHUNK  (DIM / KC)     // 32
#define THREADS 256
#define NCAND   12             // refine candidate count

// ---------------- smem layout (dynamic, bytes) ----------------
#define X_STAGE  16384                         // 64 x 64 fp32
#define W_STAGE  8192                          // 64 rows (h0 only) x 64 fp16
#define XH_STAGE 8192                          // 64 x 64 fp16 (h0 only)
#define OFF_MBAR 0
#define OFF_GB   64
#define OFF_X    1024
#define OFF_W    (OFF_X + 2 * X_STAGE)         // 33792
#define OFF_XH0  (OFF_W + 2 * W_STAGE)         // 50176
#define SMEM_TOTAL (OFF_XH0 + 2 * XH_STAGE)    // 66560 -> 2+ CTAs/SM
#define TX_BYTES (X_STAGE + W_STAGE)

// fp16 router weights (h0 of w[e][d])
__device__ __align__(1024) __half g_wh[NE * DIM];
__device__ int g_nflag;
__device__ int g_flags[16384];

// ---------------- helpers ----------------
__device__ __forceinline__ uint32_t smem_u32(const void* p) {
    uint32_t a;
    asm("{ .reg .u64 t; cvta.to.shared.u64 t, %1; cvt.u32.u64 %0, t; }" : "=r"(a) : "l"(p));
    return a;
}

#define MBAR_INIT(addr, cnt) \
    asm volatile("mbarrier.init.shared.b64 [%0], %1;" :: "r"(addr), "r"((uint32_t)(cnt)) : "memory")
#define MBAR_EXPECT_TX(addr, bytes) \
    asm volatile("mbarrier.arrive.expect_tx.shared.b64 _, [%0], %1;" :: "r"(addr), "r"((uint32_t)(bytes)) : "memory")

#define MBAR_WAIT(addr, parity) do {                                           \
    uint32_t _m = (addr); uint32_t _p = (parity); uint32_t _d;                 \
    asm volatile("{\n\t.reg .pred p;\n\t"                                      \
        "mbarrier.try_wait.parity.acquire.cta.shared::cta.b64 p, [%1], %2;\n\t"\
        "selp.b32 %0, 1, 0, p;\n\t}"                                           \
        : "=r"(_d) : "r"(_m), "r"(_p) : "memory");                             \
    if (!_d) {                                                                 \
        asm volatile("{\n\t.reg .pred P1;\n\t"                                 \
            "WL_%=:\n\t"                                                       \
            "mbarrier.try_wait.parity.acquire.cta.shared::cta.b64 P1, [%0], %1, 0x989680;\n\t" \
            "@P1 bra.uni WD_%=;\n\t"                                           \
            "bra.uni WL_%=;\n\t"                                               \
            "WD_%=:\n\t}" :: "r"(_m), "r"(_p) : "memory");                     \
    }                                                                          \
} while (0)

__device__ __forceinline__ void tma_2d(uint32_t dst, const CUtensorMap* map,
                                       int32_t cx, int32_t cy, uint32_t mbar) {
    asm volatile(
        "cp.async.bulk.tensor.2d.shared::cta.global.tile.mbarrier::complete_tx::bytes "
        "[%0], [%1, {%2, %3}], [%4];"
        :: "r"(dst), "l"(map), "r"(cx), "r"(cy), "r"(mbar) : "memory");
}

#define LDSM4(r, addr)                                                         \
    asm volatile("ldmatrix.sync.aligned.m8n8.x4.shared.b16 {%0,%1,%2,%3}, [%4];" \
        : "=r"((r)[0]), "=r"((r)[1]), "=r"((r)[2]), "=r"((r)[3]) : "r"(addr))

#define MMA16816(c, a, b0, b1)                                                 \
    asm volatile("mma.sync.aligned.m16n8k16.row.col.f32.f16.f16.f32 "          \
        "{%0,%1,%2,%3}, {%4,%5,%6,%7}, {%8,%9}, {%0,%1,%2,%3};"                \
        : "+f"((c)[0]), "+f"((c)[1]), "+f"((c)[2]), "+f"((c)[3])               \
        : "r"((a)[0]), "r"((a)[1]), "r"((a)[2]), "r"((a)[3]), "r"(b0), "r"(b1))

// SW128: 16B group g in 128B row r -> g ^ (r&7)
__device__ __forceinline__ uint32_t SWZ(int r, int k) {
    return (uint32_t)(r * 128 + ((((k) >> 3) ^ (r & 7)) << 4));
}

// ---------------- prep: w -> fp16; reset flag count ----------------
__global__ void prep_kernel(const float* __restrict__ w) {
    int i = blockIdx.x * 256 + threadIdx.x;    // 0 .. NE*DIM-1
    if (i == 0) g_nflag = 0;
    g_wh[i] = __float2half_rn(w[i]);
}

// ---------------- main gate kernel (fp16 1-term, 2 CTAs/SM) ----------------
__global__ __launch_bounds__(THREADS, 2) void gate_kernel(
    const __grid_constant__ CUtensorMap tmx,
    const __grid_constant__ CUtensorMap tmw,
    const float* __restrict__ gate_b,
    float* __restrict__ out)
{
    extern __shared__ __align__(1024) char smem[];
    const uint32_t sb = smem_u32(smem);
    const int tid = threadIdx.x;
    const int lane = tid & 31;
    const int wid = tid >> 5;
    const int tok0 = blockIdx.x * TILE_M;

    if (tid == 0) {
        MBAR_INIT(sb + OFF_MBAR + 0, 1);
        MBAR_INIT(sb + OFF_MBAR + 8, 1);
    }
    if (tid < NE) ((float*)(smem + OFF_GB))[tid] = gate_b[tid];
    __syncthreads();

    if (tid == 0) {
#pragma unroll
        for (int c = 0; c < 2; c++) {
            MBAR_EXPECT_TX(sb + OFF_MBAR + c * 8, TX_BYTES);
            tma_2d(sb + OFF_X + c * X_STAGE, &tmx, c * KC, tok0, sb + OFF_MBAR + c * 8);
            tma_2d(sb + OFF_W + c * W_STAGE, &tmw, c * KC, 0, sb + OFF_MBAR + c * 8);
        }
    }

    // warp tile: 16 tokens x 32 experts; 4 independent acc chains
    float acc[4][4];
#pragma unroll
    for (int nt = 0; nt < 4; nt++)
#pragma unroll
        for (int j = 0; j < 4; j++) acc[nt][j] = 0.f;

    const int wm = wid & 3, wn = wid >> 2;
    const int tm0 = wm * 16, en0 = wn * 32;
    const int ar = (lane & 7) + ((lane & 8) ? 8 : 0);
    const int ak = (lane & 16) ? 8 : 0;
    const int br = (lane & 7) + ((lane & 16) ? 8 : 0);
    const int bk = (lane & 8) ? 8 : 0;

    for (int c = 0; c < NCHUNK; c++) {
        const int s = c & 1, ph = (c >> 1) & 1;
        MBAR_WAIT(sb + OFF_MBAR + s * 8, ph);

        // ---- convert x fp32 -> h0 fp16 tile with SW128 ----
        {
            const char* xsrc = smem + OFF_X + s * X_STAGE;
            char* d0 = smem + OFF_XH0 + s * XH_STAGE;
#pragma unroll
            for (int i = 0; i < 8; i++) {
                int p = tid + i * THREADS;                 // pair index 0..2047
                float2 v = *(const float2*)(xsrc + p * 8);
                __half2 h0 = __float22half2_rn(v);
                int row = p >> 5, pc = p & 31;
                uint32_t off = (uint32_t)(row * 128 + ((((pc >> 2)) ^ (row & 7)) << 4) + (pc & 3) * 4);
                *(__half2*)(d0 + off) = h0;
            }
        }
        __syncthreads();

        // ---- MMA: 1 term (x0*w0) over this K=64 chunk ----
        {
            const uint32_t xh0b = sb + OFF_XH0 + s * XH_STAGE;
            const uint32_t wb = sb + OFF_W + s * W_STAGE;
#pragma unroll
            for (int ks = 0; ks < 4; ks++) {
                const int kk = ks * 16;
                uint32_t a0[4];
                LDSM4(a0, xh0b + SWZ(tm0 + ar, kk + ak));
                uint32_t b0[8];
                LDSM4(b0 + 0, wb + SWZ(en0 + br, kk + bk));
                LDSM4(b0 + 4, wb + SWZ(en0 + 16 + br, kk + bk));
#pragma unroll
                for (int nt = 0; nt < 4; nt++)
                    MMA16816(acc[nt], a0, b0[2 * nt], b0[2 * nt + 1]);
            }
        }
        __syncthreads();

        if (tid == 0 && c + 2 < NCHUNK) {
            MBAR_EXPECT_TX(sb + OFF_MBAR + s * 8, TX_BYTES);
            tma_2d(sb + OFF_X + s * X_STAGE, &tmx, (c + 2) * KC, tok0, sb + OFF_MBAR + s * 8);
            tma_2d(sb + OFF_W + s * W_STAGE, &tmw, (c + 2) * KC, 0, sb + OFF_MBAR + s * 8);
        }
    }

    // ---- epilogue: logits -> smem, then per-token sigmoid + top-8 ----
    float* sc = (float*)(smem + OFF_X);   // [64][68]
    {
        const int g = lane >> 2, q = lane & 3;
#pragma unroll
        for (int nt = 0; nt < 4; nt++) {
            int t0 = tm0 + g;
            int e0 = en0 + nt * 8 + q * 2;
            sc[t0 * 68 + e0] = acc[nt][0];
            sc[t0 * 68 + e0 + 1] = acc[nt][1];
            sc[(t0 + 8) * 68 + e0] = acc[nt][2];
            sc[(t0 + 8) * 68 + e0 + 1] = acc[nt][3];
        }
    }
    __syncthreads();

    if (tid < TILE_M) {
        const long token = tok0 + tid;
        const float* gb = (const float*)(smem + OFF_GB);
        float s[NE];
#pragma unroll
        for (int e = 0; e < NE; e++)
            s[e] = 1.f / (1.f + expf(-sc[tid * 68 + e])) + gb[e];

        float* so = out + 2L * NT * TOPK + token * NE;
#pragma unroll
        for (int i = 0; i < 16; i++)
            *(float4*)&so[4 * i] = make_float4(s[4 * i], s[4 * i + 1], s[4 * i + 2], s[4 * i + 3]);

        // top-8, strict > keeps lowest index on ties
        unsigned m0 = 0, m1 = 0;
        float wk[TOPK];
        int ik[TOPK];
        float sum = 0.f;
#pragma unroll 1
        for (int k = 0; k < TOPK; k++) {
            float best = -1e30f;
            int bi = 0;
#pragma unroll
            for (int e = 0; e < NE; e++) {
                unsigned bit = (e < 32) ? (m0 >> e) : (m1 >> (e - 32));
                if (((bit & 1u) == 0u) && (s[e] > best)) { best = s[e]; bi = e; }
            }
            if (bi < 32) m0 |= (1u << bi); else m1 |= (1u << (bi - 32));
            wk[k] = best; ik[k] = bi; sum += best;
        }
        // near-tie detection: threshold 1e-3 (~6 sigma of 1-term err diff)
        float v9 = -1e30f;
#pragma unroll
        for (int e = 0; e < NE; e++) {
            unsigned bit = (e < 32) ? (m0 >> e) : (m1 >> (e - 32));
            if (((bit & 1u) == 0u) && (s[e] > v9)) v9 = s[e];
        }
        float mingap = wk[TOPK - 1] - v9;
#pragma unroll
        for (int k = 0; k < TOPK - 1; k++) {
            float gdiff = wk[k] - wk[k + 1];
            if (gdiff < mingap) mingap = gdiff;
        }
        if (mingap < 1e-3f) {
            int ix = atomicAdd(&g_nflag, 1);
            if (ix < 16384) g_flags[ix] = (int)token;
        }

        float inv = 1.f / sum;
        *(float4*)&out[token * TOPK] = make_float4(wk[0] * inv, wk[1] * inv, wk[2] * inv, wk[3] * inv);
        *(float4*)&out[token * TOPK + 4] = make_float4(wk[4] * inv, wk[5] * inv, wk[6] * inv, wk[7] * inv);
        *(float4*)&out[NT * TOPK + token * TOPK] = make_float4((float)ik[0], (float)ik[1], (float)ik[2], (float)ik[3]);
        *(float4*)&out[NT * TOPK + token * TOPK + 4] = make_float4((float)ik[4], (float)ik[5], (float)ik[6], (float)ik[7]);
    }
}

// ---------------- refine: warp-per-token, shuffle-based, no smem ----------------
__global__ __launch_bounds__(256) void refine_kernel(
    const float* __restrict__ x,
    const float* __restrict__ w,
    const float* __restrict__ gate_b,
    float* __restrict__ out)
{
    const int lane = threadIdx.x & 31;
    const int gwarp = blockIdx.x * 8 + (threadIdx.x >> 5);
    const int nwarp = gridDim.x * 8;
    int n = g_nflag;
    if (n > 16384) n = 16384;

    for (int i = gwarp; i < n; i += nwarp) {
        const int token = g_flags[i];
        float* so = out + 2L * NT * TOPK + (long)token * NE;

        // load 64 approx scores: c0 = s[lane], c1 = s[lane+32]
        float c0 = so[lane];
        float c1 = so[lane + 32];

        // top-12 selection: 12x warp butterfly argmax (tie -> lower expert index)
        int cand[NCAND];
#pragma unroll
        for (int k = 0; k < NCAND; k++) {
            float v = (c0 >= c1) ? c0 : c1;
            int ix = (c0 >= c1) ? lane : lane + 32;
#pragma unroll
            for (int off = 16; off; off >>= 1) {
                float v2 = __shfl_xor_sync(0xFFFFFFFFu, v, off);
                int i2 = __shfl_xor_sync(0xFFFFFFFFu, ix, off);
                if (v2 > v || (v2 == v && i2 < ix)) { v = v2; ix = i2; }
            }
            cand[k] = ix;   // identical across lanes
            if (ix < 32) { if (lane == ix) c0 = -1e30f; }
            else { if (lane == ix - 32) c1 = -1e30f; }
        }

        // exact fp32 dots for 12 candidates
        const float* xr = x + (long)token * DIM;
        float ex[NCAND];
#pragma unroll 1
        for (int k = 0; k < NCAND; k++) {
            const float* wr = w + (long)cand[k] * DIM;
            float a = 0.f;
#pragma unroll 8
            for (int d = lane; d < DIM; d += 32)
                a = fmaf(xr[d], wr[d], a);
#pragma unroll
            for (int off = 16; off; off >>= 1)
                a += __shfl_xor_sync(0xFFFFFFFFu, a, off);
            float sv = 1.f / (1.f + expf(-a)) + gate_b[cand[k]];
            ex[k] = sv;
            if (lane == 0) so[cand[k]] = sv;   // exact score
        }

        // top-8 of 12 (redundant across lanes; lane 0 writes)
        unsigned used = 0;
        float wk[TOPK];
        int ik[TOPK];
        float sum = 0.f;
#pragma unroll 1
        for (int k = 0; k < TOPK; k++) {
            float best = -1e30f;
            int bc = 0;
#pragma unroll
            for (int c = 0; c < NCAND; c++) {
                if (((used >> c) & 1u) == 0u &&
                    (ex[c] > best || (ex[c] == best && cand[c] < cand[bc]))) {
                    best = ex[c]; bc = c;
                }
            }
            used |= (1u << bc);
            wk[k] = best; ik[k] = cand[bc]; sum += best;
        }
        if (lane == 0) {
            float inv = 1.f / sum;
            *(float4*)&out[(long)token * TOPK] =
                make_float4(wk[0] * inv, wk[1] * inv, wk[2] * inv, wk[3] * inv);
            *(float4*)&out[(long)token * TOPK + 4] =
                make_float4(wk[4] * inv, wk[5] * inv, wk[6] * inv, wk[7] * inv);
            *(float4*)&out[NT * TOPK + (long)token * TOPK] =
                make_float4((float)ik[0], (float)ik[1], (float)ik[2], (float)ik[3]);
            *(float4*)&out[NT * TOPK + (long)token * TOPK + 4] =
                make_float4((float)ik[4], (float)ik[5], (float)ik[6], (float)ik[7]);
        }
    }
}

// ---------------- host ----------------
typedef CUresult (*EncodeFn)(CUtensorMap*, CUtensorMapDataType, cuuint32_t, void*,
                             const cuuint64_t*, const cuuint64_t*, const cuuint32_t*,
                             const cuuint32_t*, CUtensorMapInterleave, CUtensorMapSwizzle,
                             CUtensorMapL2promotion, CUtensorMapFloatOOBfill);

static EncodeFn get_encode_fn() {
    static EncodeFn fn = nullptr;
    if (!fn) {
        void* p = nullptr;
        cudaDriverEntryPointQueryResult qr;
        cudaGetDriverEntryPoint("cuTensorMapEncodeTiled", &p, cudaEnableDefault, &qr);
        fn = (EncodeFn)p;
    }
    return fn;
}

extern "C" void kernel_launch(void* const* d_in, const int* in_sizes, int n_in,
                              void* d_out, int out_size) {
    const float* x  = (const float*)d_in[0];
    const float* w  = (const float*)d_in[1];
    const float* gb = (const float*)d_in[2];
    float* out = (float*)d_out;

    prep_kernel<<<(NE * DIM) / 256, 256>>>(w);

    void* whp = nullptr;
    cudaGetSymbolAddress(&whp, g_wh);

    EncodeFn enc = get_encode_fn();
    CUtensorMap tmx, tmw;
    {
        cuuint64_t dims[2]    = {DIM, NT};
        cuuint64_t strides[1] = {DIM * sizeof(float)};
        cuuint32_t box[2]     = {KC, TILE_M};
        cuuint32_t es[2]      = {1, 1};
        enc(&tmx, CU_TENSOR_MAP_DATA_TYPE_FLOAT32, 2, (void*)x,
            dims, strides, box, es,
            CU_TENSOR_MAP_INTERLEAVE_NONE, CU_TENSOR_MAP_SWIZZLE_NONE,
            CU_TENSOR_MAP_L2_PROMOTION_L2_128B, CU_TENSOR_MAP_FLOAT_OOB_FILL_NONE);
    }
    {
        cuuint64_t dims[2]    = {DIM, NE};
        cuuint64_t strides[1] = {DIM * sizeof(__half)};
        cuuint32_t box[2]     = {KC, NE};
        cuuint32_t es[2]      = {1, 1};
        enc(&tmw, CU_TENSOR_MAP_DATA_TYPE_FLOAT16, 2, whp,
            dims, strides, box, es,
            CU_TENSOR_MAP_INTERLEAVE_NONE, CU_TENSOR_MAP_SWIZZLE_128B,
            CU_TENSOR_MAP_L2_PROMOTION_L2_128B, CU_TENSOR_MAP_FLOAT_OOB_FILL_NONE);
    }

    cudaFuncSetAttribute(gate_kernel, cudaFuncAttributeMaxDynamicSharedMemorySize, SMEM_TOTAL);
    gate_kernel<<<NT / TILE_M, THREADS, SMEM_TOTAL>>>(tmx, tmw, gb, out);
    refine_kernel<<<1024, 256>>>(x, w, gb, out);
}

// round 16
// speedup vs baseline: 1.2489x; 1.2489x over previous
#include <cuda_runtime.h>
#include <cuda.h>
#include <cuda_fp16.h>
#include <math.h>
#include <stdint.h>

// ---------------- problem constants ----------------
#define NT      16384
#define DIM     2048
#define NE      64
#define TOPK    8
#define TILE_M  64
#define KC      64
#define NCHUNK  (DIM / KC)     // 32
#define THREADS 256
#define NCAND   10             // refine candidate pool (top-10)
#define TIGHT_TH 1e-3f

// ---------------- smem layout (dynamic, bytes) ----------------
#define X_STAGE  16384                         // 64 x 64 fp32
#define W_STAGE  8192                          // 64 rows x 64 fp16
#define XH_STAGE 8192                          // 64 x 64 fp16
#define OFF_MBAR 0
#define OFF_GB   64
#define OFF_X    1024
#define OFF_W    (OFF_X + 2 * X_STAGE)         // 33792
#define OFF_XH0  (OFF_W + 2 * W_STAGE)         // 50176
#define SMEM_TOTAL (OFF_XH0 + 2 * XH_STAGE)    // 66560
#define TX_BYTES (X_STAGE + W_STAGE)

// fp16 router weights
__device__ __align__(1024) __half g_wh[NE * DIM];
__device__ int g_nflag;
__device__ int g_flags[16384];

// ---------------- helpers ----------------
__device__ __forceinline__ uint32_t smem_u32(const void* p) {
    uint32_t a;
    asm("{ .reg .u64 t; cvta.to.shared.u64 t, %1; cvt.u32.u64 %0, t; }" : "=r"(a) : "l"(p));
    return a;
}

#define MBAR_INIT(addr, cnt) \
    asm volatile("mbarrier.init.shared.b64 [%0], %1;" :: "r"(addr), "r"((uint32_t)(cnt)) : "memory")
#define MBAR_EXPECT_TX(addr, bytes) \
    asm volatile("mbarrier.arrive.expect_tx.shared.b64 _, [%0], %1;" :: "r"(addr), "r"((uint32_t)(bytes)) : "memory")

#define MBAR_WAIT(addr, parity) do {                                           \
    uint32_t _m = (addr); uint32_t _p = (parity); uint32_t _d;                 \
    asm volatile("{\n\t.reg .pred p;\n\t"                                      \
        "mbarrier.try_wait.parity.acquire.cta.shared::cta.b64 p, [%1], %2;\n\t"\
        "selp.b32 %0, 1, 0, p;\n\t}"                                           \
        : "=r"(_d) : "r"(_m), "r"(_p) : "memory");                             \
    if (!_d) {                                                                 \
        asm volatile("{\n\t.reg .pred P1;\n\t"                                 \
            "WL_%=:\n\t"                                                       \
            "mbarrier.try_wait.parity.acquire.cta.shared::cta.b64 P1, [%0], %1, 0x989680;\n\t" \
            "@P1 bra.uni WD_%=;\n\t"                                           \
            "bra.uni WL_%=;\n\t"                                               \
            "WD_%=:\n\t}" :: "r"(_m), "r"(_p) : "memory");                     \
    }                                                                          \
} while (0)

__device__ __forceinline__ void tma_2d(uint32_t dst, const CUtensorMap* map,
                                       int32_t cx, int32_t cy, uint32_t mbar) {
    asm volatile(
        "cp.async.bulk.tensor.2d.shared::cta.global.tile.mbarrier::complete_tx::bytes "
        "[%0], [%1, {%2, %3}], [%4];"
        :: "r"(dst), "l"(map), "r"(cx), "r"(cy), "r"(mbar) : "memory");
}

#define LDSM4(r, addr)                                                         \
    asm volatile("ldmatrix.sync.aligned.m8n8.x4.shared.b16 {%0,%1,%2,%3}, [%4];" \
        : "=r"((r)[0]), "=r"((r)[1]), "=r"((r)[2]), "=r"((r)[3]) : "r"(addr))

#define MMA16816(c, a, b0, b1)                                                 \
    asm volatile("mma.sync.aligned.m16n8k16.row.col.f32.f16.f16.f32 "          \
        "{%0,%1,%2,%3}, {%4,%5,%6,%7}, {%8,%9}, {%0,%1,%2,%3};"                \
        : "+f"((c)[0]), "+f"((c)[1]), "+f"((c)[2]), "+f"((c)[3])               \
        : "r"((a)[0]), "r"((a)[1]), "r"((a)[2]), "r"((a)[3]), "r"(b0), "r"(b1))

// SW128: 16B group g in 128B row r -> g ^ (r&7)
__device__ __forceinline__ uint32_t SWZ(int r, int k) {
    return (uint32_t)(r * 128 + ((((k) >> 3) ^ (r & 7)) << 4));
}

// ---------------- prep: w -> fp16; reset flag count ----------------
__global__ void prep_kernel(const float* __restrict__ w) {
    int i = blockIdx.x * 256 + threadIdx.x;    // 0 .. NE*DIM-1
    if (i == 0) g_nflag = 0;
    g_wh[i] = __float2half_rn(w[i]);
}

// ---------------- main gate kernel (fp16 1-term, 2 CTAs/SM) ----------------
__global__ __launch_bounds__(THREADS, 2) void gate_kernel(
    const __grid_constant__ CUtensorMap tmx,
    const __grid_constant__ CUtensorMap tmw,
    const float* __restrict__ gate_b,
    float* __restrict__ out)
{
    extern __shared__ __align__(1024) char smem[];
    const uint32_t sb = smem_u32(smem);
    const int tid = threadIdx.x;
    const int lane = tid & 31;
    const int wid = tid >> 5;
    const int tok0 = blockIdx.x * TILE_M;

    if (tid == 0) {
        MBAR_INIT(sb + OFF_MBAR + 0, 1);
        MBAR_INIT(sb + OFF_MBAR + 8, 1);
    }
    if (tid < NE) ((float*)(smem + OFF_GB))[tid] = gate_b[tid];
    __syncthreads();

    if (tid == 0) {
#pragma unroll
        for (int c = 0; c < 2; c++) {
            MBAR_EXPECT_TX(sb + OFF_MBAR + c * 8, TX_BYTES);
            tma_2d(sb + OFF_X + c * X_STAGE, &tmx, c * KC, tok0, sb + OFF_MBAR + c * 8);
            tma_2d(sb + OFF_W + c * W_STAGE, &tmw, c * KC, 0, sb + OFF_MBAR + c * 8);
        }
    }

    float acc[4][4];
#pragma unroll
    for (int nt = 0; nt < 4; nt++)
#pragma unroll
        for (int j = 0; j < 4; j++) acc[nt][j] = 0.f;

    const int wm = wid & 3, wn = wid >> 2;
    const int tm0 = wm * 16, en0 = wn * 32;
    const int ar = (lane & 7) + ((lane & 8) ? 8 : 0);
    const int ak = (lane & 16) ? 8 : 0;
    const int br = (lane & 7) + ((lane & 16) ? 8 : 0);
    const int bk = (lane & 8) ? 8 : 0;

    for (int c = 0; c < NCHUNK; c++) {
        const int s = c & 1, ph = (c >> 1) & 1;
        MBAR_WAIT(sb + OFF_MBAR + s * 8, ph);

        // ---- convert x fp32 -> h0 fp16 tile with SW128 ----
        {
            const char* xsrc = smem + OFF_X + s * X_STAGE;
            char* d0 = smem + OFF_XH0 + s * XH_STAGE;
#pragma unroll
            for (int i = 0; i < 8; i++) {
                int p = tid + i * THREADS;                 // pair index 0..2047
                float2 v = *(const float2*)(xsrc + p * 8);
                __half2 h0 = __float22half2_rn(v);
                int row = p >> 5, pc = p & 31;
                uint32_t off = (uint32_t)(row * 128 + ((((pc >> 2)) ^ (row & 7)) << 4) + (pc & 3) * 4);
                *(__half2*)(d0 + off) = h0;
            }
        }
        __syncthreads();

        // ---- MMA: 1 term (x0*w0) over this K=64 chunk ----
        {
            const uint32_t xh0b = sb + OFF_XH0 + s * XH_STAGE;
            const uint32_t wb = sb + OFF_W + s * W_STAGE;
#pragma unroll
            for (int ks = 0; ks < 4; ks++) {
                const int kk = ks * 16;
                uint32_t a0[4];
                LDSM4(a0, xh0b + SWZ(tm0 + ar, kk + ak));
                uint32_t b0[8];
                LDSM4(b0 + 0, wb + SWZ(en0 + br, kk + bk));
                LDSM4(b0 + 4, wb + SWZ(en0 + 16 + br, kk + bk));
#pragma unroll
                for (int nt = 0; nt < 4; nt++)
                    MMA16816(acc[nt], a0, b0[2 * nt], b0[2 * nt + 1]);
            }
        }
        __syncthreads();

        if (tid == 0 && c + 2 < NCHUNK) {
            MBAR_EXPECT_TX(sb + OFF_MBAR + s * 8, TX_BYTES);
            tma_2d(sb + OFF_X + s * X_STAGE, &tmx, (c + 2) * KC, tok0, sb + OFF_MBAR + s * 8);
            tma_2d(sb + OFF_W + s * W_STAGE, &tmw, (c + 2) * KC, 0, sb + OFF_MBAR + s * 8);
        }
    }

    // ---- epilogue ----
    float* sc = (float*)(smem + OFF_X);   // [64][68]
    {
        const int g = lane >> 2, q = lane & 3;
#pragma unroll
        for (int nt = 0; nt < 4; nt++) {
            int t0 = tm0 + g;
            int e0 = en0 + nt * 8 + q * 2;
            sc[t0 * 68 + e0] = acc[nt][0];
            sc[t0 * 68 + e0 + 1] = acc[nt][1];
            sc[(t0 + 8) * 68 + e0] = acc[nt][2];
            sc[(t0 + 8) * 68 + e0 + 1] = acc[nt][3];
        }
    }
    __syncthreads();

    if (tid < TILE_M) {
        const long token = tok0 + tid;
        const float* gb = (const float*)(smem + OFF_GB);
        float s[NE];
#pragma unroll
        for (int e = 0; e < NE; e++)
            s[e] = 1.f / (1.f + expf(-sc[tid * 68 + e])) + gb[e];

        float* so = out + 2L * NT * TOPK + token * NE;
#pragma unroll
        for (int i = 0; i < 16; i++)
            *(float4*)&so[4 * i] = make_float4(s[4 * i], s[4 * i + 1], s[4 * i + 2], s[4 * i + 3]);

        // top-8, strict > keeps lowest index on ties
        unsigned m0 = 0, m1 = 0;
        float wk[TOPK];
        int ik[TOPK];
        float sum = 0.f;
#pragma unroll 1
        for (int k = 0; k < TOPK; k++) {
            float best = -1e30f;
            int bi = 0;
#pragma unroll
            for (int e = 0; e < NE; e++) {
                unsigned bit = (e < 32) ? (m0 >> e) : (m1 >> (e - 32));
                if (((bit & 1u) == 0u) && (s[e] > best)) { best = s[e]; bi = e; }
            }
            if (bi < 32) m0 |= (1u << bi); else m1 |= (1u << (bi - 32));
            wk[k] = best; ik[k] = bi; sum += best;
        }
        // near-tie detection (incl. rank-8/9 boundary)
        float v9 = -1e30f;
#pragma unroll
        for (int e = 0; e < NE; e++) {
            unsigned bit = (e < 32) ? (m0 >> e) : (m1 >> (e - 32));
            if (((bit & 1u) == 0u) && (s[e] > v9)) v9 = s[e];
        }
        float mingap = wk[TOPK - 1] - v9;
#pragma unroll
        for (int k = 0; k < TOPK - 1; k++) {
            float gdiff = wk[k] - wk[k + 1];
            if (gdiff < mingap) mingap = gdiff;
        }
        if (mingap < TIGHT_TH) {
            int ix = atomicAdd(&g_nflag, 1);
            if (ix < 16384) g_flags[ix] = (int)token;
        }

        float inv = 1.f / sum;
        *(float4*)&out[token * TOPK] = make_float4(wk[0] * inv, wk[1] * inv, wk[2] * inv, wk[3] * inv);
        *(float4*)&out[token * TOPK + 4] = make_float4(wk[4] * inv, wk[5] * inv, wk[6] * inv, wk[7] * inv);
        *(float4*)&out[NT * TOPK + token * TOPK] = make_float4((float)ik[0], (float)ik[1], (float)ik[2], (float)ik[3]);
        *(float4*)&out[NT * TOPK + token * TOPK + 4] = make_float4((float)ik[4], (float)ik[5], (float)ik[6], (float)ik[7]);
    }
}

// ---------------- refine v4: warp-per-token, exact dots ONLY for tight pairs ----------------
__global__ __launch_bounds__(256) void refine_kernel(
    const float* __restrict__ x,
    const float* __restrict__ w,
    const float* __restrict__ gate_b,
    float* __restrict__ out)
{
    const int lane = threadIdx.x & 31;
    const int gwarp = blockIdx.x * 8 + (threadIdx.x >> 5);
    const int nwarp = gridDim.x * 8;
    int n = g_nflag;
    if (n > 16384) n = 16384;

    for (int i = gwarp; i < n; i += nwarp) {
        const int token = g_flags[i];
        const float* so = out + 2L * NT * TOPK + (long)token * NE;

        float c0 = so[lane];
        float c1 = so[lane + 32];

        // top-10 approx selection (butterfly argmax, tie -> lower index)
        float val[NCAND];
        int cand[NCAND];
#pragma unroll
        for (int k = 0; k < NCAND; k++) {
            float v = (c0 >= c1) ? c0 : c1;
            int ix = (c0 >= c1) ? lane : lane + 32;
#pragma unroll
            for (int off = 16; off; off >>= 1) {
                float v2 = __shfl_xor_sync(0xFFFFFFFFu, v, off);
                int i2 = __shfl_xor_sync(0xFFFFFFFFu, ix, off);
                if (v2 > v || (v2 == v && i2 < ix)) { v = v2; ix = i2; }
            }
            val[k] = v; cand[k] = ix;
            if (ix < 32) { if (lane == ix) c0 = -1e30f; }
            else { if (lane == ix - 32) c1 = -1e30f; }
        }

        // tight candidates: adjacent (in rank order) gap < TIGHT_TH
        bool tight[NCAND];
#pragma unroll
        for (int k = 0; k < NCAND; k++) {
            bool t = false;
            if (k > 0 && (val[k - 1] - val[k]) < TIGHT_TH) t = true;
            if (k < NCAND - 1 && (val[k] - val[k + 1]) < TIGHT_TH) t = true;
            tight[k] = t;
        }

        // exact fp32 dots only for tight candidates
        const float* xr = x + (long)token * DIM;
#pragma unroll
        for (int k = 0; k < NCAND; k++) {
            if (tight[k]) {
                const float* wr = w + (long)cand[k] * DIM;
                float a = 0.f;
#pragma unroll 8
                for (int d = lane; d < DIM; d += 32)
                    a = fmaf(xr[d], wr[d], a);
#pragma unroll
                for (int off = 16; off; off >>= 1)
                    a += __shfl_xor_sync(0xFFFFFFFFu, a, off);
                val[k] = 1.f / (1.f + expf(-a)) + gate_b[cand[k]];
            }
        }

        // top-8 of 10 patched scores (tie -> lower expert index)
        unsigned used = 0;
        float wk[TOPK];
        int ik[TOPK];
        float sum = 0.f;
#pragma unroll 1
        for (int k = 0; k < TOPK; k++) {
            float best = -1e30f;
            int bc = 0;
#pragma unroll
            for (int c = 0; c < NCAND; c++) {
                if (((used >> c) & 1u) == 0u &&
                    (val[c] > best || (val[c] == best && cand[c] < cand[bc]))) {
                    best = val[c]; bc = c;
                }
            }
            used |= (1u << bc);
            wk[k] = best; ik[k] = cand[bc]; sum += best;
        }
        if (lane == 0) {
            float inv = 1.f / sum;
            *(float4*)&out[(long)token * TOPK] =
                make_float4(wk[0] * inv, wk[1] * inv, wk[2] * inv, wk[3] * inv);
            *(float4*)&out[(long)token * TOPK + 4] =
                make_float4(wk[4] * inv, wk[5] * inv, wk[6] * inv, wk[7] * inv);
            *(float4*)&out[NT * TOPK + (long)token * TOPK] =
                make_float4((float)ik[0], (float)ik[1], (float)ik[2], (float)ik[3]);
            *(float4*)&out[NT * TOPK + (long)token * TOPK + 4] =
                make_float4((float)ik[4], (float)ik[5], (float)ik[6], (float)ik[7]);
        }
    }
}

// ---------------- host ----------------
typedef CUresult (*EncodeFn)(CUtensorMap*, CUtensorMapDataType, cuuint32_t, void*,
                             const cuuint64_t*, const cuuint64_t*, const cuuint32_t*,
                             const cuuint32_t*, CUtensorMapInterleave, CUtensorMapSwizzle,
                             CUtensorMapL2promotion, CUtensorMapFloatOOBfill);

static EncodeFn get_encode_fn() {
    static EncodeFn fn = nullptr;
    if (!fn) {
        void* p = nullptr;
        cudaDriverEntryPointQueryResult qr;
        cudaGetDriverEntryPoint("cuTensorMapEncodeTiled", &p, cudaEnableDefault, &qr);
        fn = (EncodeFn)p;
    }
    return fn;
}

extern "C" void kernel_launch(void* const* d_in, const int* in_sizes, int n_in,
                              void* d_out, int out_size) {
    const float* x  = (const float*)d_in[0];
    const float* w  = (const float*)d_in[1];
    const float* gb = (const float*)d_in[2];
    float* out = (float*)d_out;

    prep_kernel<<<(NE * DIM) / 256, 256>>>(w);

    void* whp = nullptr;
    cudaGetSymbolAddress(&whp, g_wh);

    EncodeFn enc = get_encode_fn();
    CUtensorMap tmx, tmw;
    {
        cuuint64_t dims[2]    = {DIM, NT};
        cuuint64_t strides[1] = {DIM * sizeof(float)};
        cuuint32_t box[2]     = {KC, TILE_M};
        cuuint32_t es[2]      = {1, 1};
        enc(&tmx, CU_TENSOR_MAP_DATA_TYPE_FLOAT32, 2, (void*)x,
            dims, strides, box, es,
            CU_TENSOR_MAP_INTERLEAVE_NONE, CU_TENSOR_MAP_SWIZZLE_NONE,
            CU_TENSOR_MAP_L2_PROMOTION_L2_128B, CU_TENSOR_MAP_FLOAT_OOB_FILL_NONE);
    }
    {
        cuuint64_t dims[2]    = {DIM, NE};
        cuuint64_t strides[1] = {DIM * sizeof(__half)};
        cuuint32_t box[2]     = {KC, NE};
        cuuint32_t es[2]      = {1, 1};
        enc(&tmw, CU_TENSOR_MAP_DATA_TYPE_FLOAT16, 2, whp,
            dims, strides, box, es,
            CU_TENSOR_MAP_INTERLEAVE_NONE, CU_TENSOR_MAP_SWIZZLE_128B,
            CU_TENSOR_MAP_L2_PROMOTION_L2_128B, CU_TENSOR_MAP_FLOAT_OOB_FILL_NONE);
    }

    cudaFuncSetAttribute(gate_kernel, cudaFuncAttributeMaxDynamicSharedMemorySize, SMEM_TOTAL);
    gate_kernel<<<NT / TILE_M, THREADS, SMEM_TOTAL>>>(tmx, tmw, gb, out);
    refine_kernel<<<1024, 256>>>(x, w, gb, out);
}